// round 15
// baseline (speedup 1.0000x reference)
#include <cuda_runtime.h>
#include <cuda_bf16.h>
#include <math.h>
#include <stdint.h>

#define NN 100000
#define EE 1600000
#define DD 128
#define LL 4
#define GG 512
#define BN_EPS 1e-5f
#define NPAD 100096
#define NSM_MAX 160

// ---------------- device scratch (no allocations allowed) ----------------
static __device__ __align__(16) float g_h[(size_t)NN * DD];
static __device__ __align__(16) unsigned short g_zh[(size_t)NPAD * DD];
static __device__ __align__(16) unsigned short g_zl[(size_t)NPAD * DD];
static __device__ __align__(16) unsigned short g_yh[(size_t)NPAD * DD];
static __device__ __align__(16) unsigned short g_yl[(size_t)NPAD * DD];
static __device__ float g_scale[DD];
static __device__ float g_shift[DD];
static __device__ __align__(16) unsigned short g_Bhi[8][DD * DD];
static __device__ __align__(16) unsigned short g_Blo[8][DD * DD];
static __device__ float g_part[NSM_MAX][2 * DD];
static __device__ int g_done;            // monotonic epoch counter (mod-nsm)
// CSR scratch
static __device__ int g_deg[NN];
static __device__ int g_rowptr[NN + 1];
static __device__ int g_cursor[NN];
static __device__ int g_csr_src[EE];
static __device__ int g_bsum[256];
static __device__ int g_boff[256];

#define SCAN_BLK 512
#define NBLK_SCAN ((NN + SCAN_BLK - 1) / SCAN_BLK)

__device__ __forceinline__ float elu_f(float x) {
    return x > 0.f ? x : expm1f(x);
}
__device__ __forceinline__ uint32_t smem_u32(const void* p) {
    uint32_t a;
    asm("{ .reg .u64 t; cvta.to.shared.u64 t, %1; cvt.u32.u64 %0, t; }" : "=r"(a) : "l"(p));
    return a;
}
__device__ __forceinline__ uint32_t pack_bf16x2(float lo, float hi) {
    uint32_t r;
    asm("cvt.rn.bf16x2.f32 %0, %1, %2;" : "=r"(r) : "f"(hi), "f"(lo));
    return r;
}
__device__ __forceinline__ void cp16(uint32_t dst, const void* src) {
    asm volatile("cp.async.cg.shared.global [%0], [%1], 16;" :: "r"(dst), "l"(src));
}
#define CP_COMMIT() asm volatile("cp.async.commit_group;")
#define CP_WAIT0()  asm volatile("cp.async.wait_group 0;")

__device__ __forceinline__ void ldsm_x4(uint32_t* r, uint32_t addr) {
    asm volatile("ldmatrix.sync.aligned.m8n8.x4.shared.b16 {%0,%1,%2,%3}, [%4];"
                 : "=r"(r[0]), "=r"(r[1]), "=r"(r[2]), "=r"(r[3]) : "r"(addr));
}
__device__ __forceinline__ void ldsm_x2(uint32_t* r, uint32_t addr) {
    asm volatile("ldmatrix.sync.aligned.m8n8.x2.shared.b16 {%0,%1}, [%2];"
                 : "=r"(r[0]), "=r"(r[1]) : "r"(addr));
}
__device__ __forceinline__ void mma_bf16(float* c, const uint32_t* a, const uint32_t* b) {
    asm volatile(
        "mma.sync.aligned.m16n8k16.row.col.f32.bf16.bf16.f32 "
        "{%0,%1,%2,%3}, {%4,%5,%6,%7}, {%8,%9}, {%0,%1,%2,%3};"
        : "+f"(c[0]), "+f"(c[1]), "+f"(c[2]), "+f"(c[3])
        : "r"(a[0]), "r"(a[1]), "r"(a[2]), "r"(a[3]), "r"(b[0]), "r"(b[1]));
}

// ------- weight conversion (y<8) + CSR degree zero (y==8), one launch ----
__global__ void convert_weights(const float* __restrict__ W1, const float* __restrict__ W2) {
    int idx = blockIdx.x * blockDim.x + threadIdx.x;
    if (blockIdx.y == 8) {
        if (idx < NN) g_deg[idx] = 0;
        return;
    }
    if (idx >= DD * DD) return;
    int mat = blockIdx.y;
    const float* W = (mat & 1) ? (W2 + (size_t)(mat >> 1) * DD * DD)
                               : (W1 + (size_t)(mat >> 1) * DD * DD);
    int n = idx / DD, k = idx % DD;
    float w = W[k * DD + n];
    uint32_t p = pack_bf16x2(w, 0.f);
    uint32_t hb = p & 0xFFFFu;
    float hf = __uint_as_float(hb << 16);
    uint32_t pl = pack_bf16x2(w - hf, 0.f);
    g_Bhi[mat][n * DD + k] = (unsigned short)hb;
    g_Blo[mat][n * DD + k] = (unsigned short)(pl & 0xFFFFu);
}

// ---------------- CSR build ----------------
__global__ void csr_hist(const int* __restrict__ ei) {
    int e = blockIdx.x * blockDim.x + threadIdx.x;
    if (e < EE) atomicAdd(&g_deg[ei[EE + e]], 1);
}
__global__ void scanA() {
    __shared__ int s[SCAN_BLK];
    int b = blockIdx.x, t = threadIdx.x;
    int i = b * SCAN_BLK + t;
    int v = (i < NN) ? g_deg[i] : 0;
    s[t] = v;
    __syncthreads();
#pragma unroll
    for (int off = 1; off < SCAN_BLK; off <<= 1) {
        int u = (t >= off) ? s[t - off] : 0;
        __syncthreads();
        s[t] += u;
        __syncthreads();
    }
    if (i < NN) g_rowptr[i] = s[t] - v;
    if (t == SCAN_BLK - 1) g_bsum[b] = s[t];
}
__global__ void scanB() {
    __shared__ int s[256];
    int t = threadIdx.x;
    int v = (t < NBLK_SCAN) ? g_bsum[t] : 0;
    s[t] = v;
    __syncthreads();
#pragma unroll
    for (int off = 1; off < 256; off <<= 1) {
        int u = (t >= off) ? s[t - off] : 0;
        __syncthreads();
        s[t] += u;
        __syncthreads();
    }
    if (t < NBLK_SCAN) g_boff[t] = s[t] - v;
}
__global__ void scanC() {
    int i = blockIdx.x * blockDim.x + threadIdx.x;
    if (i < NN) {
        int r = g_rowptr[i] + g_boff[i / SCAN_BLK];
        g_rowptr[i] = r;
        g_cursor[i] = r;
    }
    if (i == 0) g_rowptr[NN] = EE;
}
__global__ void csr_fill(const int* __restrict__ ei) {
    int e = blockIdx.x * blockDim.x + threadIdx.x;
    if (e < EE) {
        int dst = ei[EE + e];
        int pos = atomicAdd(&g_cursor[dst], 1);
        g_csr_src[pos] = ei[e];
    }
}

// ------- aggregation: z[i] = H[i] + sum H[j], split-bf16 out -------------
__global__ void gather_agg(const float* __restrict__ H) {
    long tid = (long)blockIdx.x * blockDim.x + threadIdx.x;
    int node = (int)(tid >> 5);
    if (node >= NN) return;
    int c = (int)(tid & 31) << 2;
    float4 acc = *(const float4*)&H[(size_t)node * DD + c];
    int lo = __ldg(&g_rowptr[node]);
    int hi = __ldg(&g_rowptr[node + 1]);
    int j = lo;
    int s_next = (j < hi) ? __ldg(&g_csr_src[j]) : 0;
    while (j < hi) {
        int s = s_next;
        ++j;
        if (j < hi) s_next = __ldg(&g_csr_src[j]);
        float4 v = *(const float4*)&H[(size_t)s * DD + c];
        acc.x += v.x; acc.y += v.y; acc.z += v.z; acc.w += v.w;
    }
    uint32_t h01 = pack_bf16x2(acc.x, acc.y);
    uint32_t h23 = pack_bf16x2(acc.z, acc.w);
    float ax = __uint_as_float(h01 << 16);
    float ay = __uint_as_float(h01 & 0xFFFF0000u);
    float az = __uint_as_float(h23 << 16);
    float aw = __uint_as_float(h23 & 0xFFFF0000u);
    uint32_t l01 = pack_bf16x2(acc.x - ax, acc.y - ay);
    uint32_t l23 = pack_bf16x2(acc.z - az, acc.w - aw);
    *(uint2*)&g_zh[(size_t)node * DD + c] = make_uint2(h01, h23);
    *(uint2*)&g_zl[(size_t)node * DD + c] = make_uint2(l01, l23);
}

// ---------------- persistent HMMA GEMM -----------------------------------
#define TSTRIDE 136
#define PTILE (128 * TSTRIDE * 2)
#define OFF_BH 0
#define OFF_BL PTILE
#define OFF_A0 (2 * PTILE)
#define OFF_A1 (4 * PTILE)
#define SMEM_MMA_BYTES (6 * PTILE)
#define NT ((NN + 127) / 128)

template <int MODE>
__global__ __launch_bounds__(256, 1) void mma_gemm(const unsigned short* __restrict__ Bhi,
                                                   const unsigned short* __restrict__ Blo,
                                                   const float* __restrict__ bias,
                                                   const float* __restrict__ gamma,
                                                   const float* __restrict__ beta,
                                                   int nsm) {
    extern __shared__ char smem[];
    __shared__ float s_bn[2 * DD];
    __shared__ float s_scale[DD], s_shift[DD];
    __shared__ int s_last;

    const int tid = threadIdx.x;
    const int wid = tid >> 5;
    const int lane = tid & 31;
    const uint32_t sbase = smem_u32(smem);

    const unsigned short* AH = (MODE == 0) ? g_zh : g_yh;
    const unsigned short* AL = (MODE == 0) ? g_zl : g_yl;

    if (MODE == 0) { s_bn[tid] = 0.f; }
    if (MODE == 1 && tid < DD) { s_scale[tid] = g_scale[tid]; s_shift[tid] = g_shift[tid]; }

#pragma unroll
    for (int it = 0; it < 8; it++) {
        int i = tid + it * 256;
        int r = i >> 4;
        int ci = (i & 15) * 16;
        cp16(sbase + OFF_BH + r * 272 + ci, (const char*)Bhi + r * 256 + ci);
        cp16(sbase + OFF_BL + r * 272 + ci, (const char*)Blo + r * 256 + ci);
    }
    int t = blockIdx.x;
    if (t < NT) {
        const unsigned short* srcH = AH + (size_t)t * 128 * DD;
        const unsigned short* srcL = AL + (size_t)t * 128 * DD;
#pragma unroll
        for (int it = 0; it < 8; it++) {
            int i = tid + it * 256;
            int r = i >> 4;
            int ci = (i & 15) * 16;
            cp16(sbase + OFF_A0 + r * 272 + ci, (const char*)srcH + r * 256 + ci);
            cp16(sbase + OFF_A0 + PTILE + r * 272 + ci, (const char*)srcL + r * 256 + ci);
        }
    }
    CP_COMMIT();
    CP_WAIT0();
    __syncthreads();

    const int wm = wid >> 2;
    const int wn = wid & 3;
    const int a_row = wm * 64 + (lane & 15);
    const int a_colsel = (lane >> 4) * 8;
    const int b_row = wn * 32 + (lane & 7);
    const int b_colsel = ((lane >> 3) & 1) * 8;
    const int ep_r = wm * 64 + (lane >> 2);
    const int cbase = wn * 32 + (lane & 3) * 2;

    float bv0[4], bv1[4];
#pragma unroll
    for (int ni = 0; ni < 4; ni++) {
        bv0[ni] = __ldg(&bias[cbase + ni * 8]);
        bv1[ni] = __ldg(&bias[cbase + ni * 8 + 1]);
    }

    float ps[8], pq[8];
#pragma unroll
    for (int j = 0; j < 8; j++) { ps[j] = 0.f; pq[j] = 0.f; }

    int stage = 0;
    while (t < NT) {
        int tn = t + gridDim.x;
        const uint32_t curA = sbase + (stage ? OFF_A1 : OFF_A0);
        const uint32_t nxtA = sbase + (stage ? OFF_A0 : OFF_A1);
        if (tn < NT) {
            const unsigned short* srcH = AH + (size_t)tn * 128 * DD;
            const unsigned short* srcL = AL + (size_t)tn * 128 * DD;
#pragma unroll
            for (int it = 0; it < 8; it++) {
                int i = tid + it * 256;
                int r = i >> 4;
                int ci = (i & 15) * 16;
                cp16(nxtA + r * 272 + ci, (const char*)srcH + r * 256 + ci);
                cp16(nxtA + PTILE + r * 272 + ci, (const char*)srcL + r * 256 + ci);
            }
        }
        CP_COMMIT();

        if (MODE == 1) {
#pragma unroll
            for (int it = 0; it < 8; it++) {
                int i = tid + it * 256;
                int r = i >> 4;
                int ci = (i & 15) * 16;
                uint32_t ah = curA + r * 272 + ci;
                uint32_t al = ah + PTILE;
                uint4 hv = *(uint4*)(smem + (ah - sbase));
                uint4 lv = *(uint4*)(smem + (al - sbase));
                uint32_t* hw = (uint32_t*)&hv;
                uint32_t* lw = (uint32_t*)&lv;
                int col0 = ci >> 1;
#pragma unroll
                for (int w = 0; w < 4; w++) {
                    int col = col0 + w * 2;
                    float v0 = __uint_as_float(hw[w] << 16) + __uint_as_float(lw[w] << 16);
                    float v1 = __uint_as_float(hw[w] & 0xFFFF0000u) +
                               __uint_as_float(lw[w] & 0xFFFF0000u);
                    v0 = elu_f(v0 * s_scale[col] + s_shift[col]);
                    v1 = elu_f(v1 * s_scale[col + 1] + s_shift[col + 1]);
                    uint32_t hp = pack_bf16x2(v0, v1);
                    float r0 = __uint_as_float(hp << 16);
                    float r1 = __uint_as_float(hp & 0xFFFF0000u);
                    hw[w] = hp;
                    lw[w] = pack_bf16x2(v0 - r0, v1 - r1);
                }
                *(uint4*)(smem + (ah - sbase)) = hv;
                *(uint4*)(smem + (al - sbase)) = lv;
            }
            __syncthreads();
        }

        float acc[4][4][4];
#pragma unroll
        for (int mi = 0; mi < 4; mi++)
#pragma unroll
            for (int ni = 0; ni < 4; ni++)
#pragma unroll
                for (int q = 0; q < 4; q++) acc[mi][ni][q] = 0.f;

#pragma unroll
        for (int ks = 0; ks < 8; ks++) {
            uint32_t a[4][4];
#pragma unroll
            for (int mi = 0; mi < 4; mi++)
                ldsm_x4(a[mi], curA + (uint32_t)((a_row + mi * 16) * TSTRIDE
                                                 + ks * 16 + a_colsel) * 2);
            uint32_t b[4][2];
#pragma unroll
            for (int ni = 0; ni < 4; ni++)
                ldsm_x2(b[ni], sbase + OFF_BH + (uint32_t)((b_row + ni * 8) * TSTRIDE
                                                           + ks * 16 + b_colsel) * 2);
#pragma unroll
            for (int mi = 0; mi < 4; mi++)
#pragma unroll
                for (int ni = 0; ni < 4; ni++)
                    mma_bf16(acc[mi][ni], a[mi], b[ni]);
#pragma unroll
            for (int ni = 0; ni < 4; ni++)
                ldsm_x2(b[ni], sbase + OFF_BL + (uint32_t)((b_row + ni * 8) * TSTRIDE
                                                           + ks * 16 + b_colsel) * 2);
#pragma unroll
            for (int mi = 0; mi < 4; mi++)
#pragma unroll
                for (int ni = 0; ni < 4; ni++)
                    mma_bf16(acc[mi][ni], a[mi], b[ni]);
        }
#pragma unroll
        for (int ks = 0; ks < 8; ks++) {
            uint32_t a[4][4];
#pragma unroll
            for (int mi = 0; mi < 4; mi++)
                ldsm_x4(a[mi], curA + PTILE + (uint32_t)((a_row + mi * 16) * TSTRIDE
                                                         + ks * 16 + a_colsel) * 2);
            uint32_t b[4][2];
#pragma unroll
            for (int ni = 0; ni < 4; ni++)
                ldsm_x2(b[ni], sbase + OFF_BH + (uint32_t)((b_row + ni * 8) * TSTRIDE
                                                           + ks * 16 + b_colsel) * 2);
#pragma unroll
            for (int mi = 0; mi < 4; mi++)
#pragma unroll
                for (int ni = 0; ni < 4; ni++)
                    mma_bf16(acc[mi][ni], a[mi], b[ni]);
        }

        const int rowBase = t * 128;
#pragma unroll
        for (int ni = 0; ni < 4; ni++) {
            int col = cbase + ni * 8;
#pragma unroll
            for (int mi = 0; mi < 4; mi++) {
                int gr0 = rowBase + ep_r + mi * 16;
                float v0 = acc[mi][ni][0] + bv0[ni];
                float v1 = acc[mi][ni][1] + bv1[ni];
                float v2 = acc[mi][ni][2] + bv0[ni];
                float v3 = acc[mi][ni][3] + bv1[ni];
                if (MODE == 0) {
                    if (gr0 < NN) {
                        ps[ni * 2 + 0] += v0; ps[ni * 2 + 1] += v1;
                        pq[ni * 2 + 0] += v0 * v0; pq[ni * 2 + 1] += v1 * v1;
                        uint32_t hp = pack_bf16x2(v0, v1);
                        float h0 = __uint_as_float(hp << 16);
                        float h1 = __uint_as_float(hp & 0xFFFF0000u);
                        *(uint32_t*)&g_yh[(size_t)gr0 * DD + col] = hp;
                        *(uint32_t*)&g_yl[(size_t)gr0 * DD + col] = pack_bf16x2(v0 - h0, v1 - h1);
                    }
                    if (gr0 + 8 < NN) {
                        ps[ni * 2 + 0] += v2; ps[ni * 2 + 1] += v3;
                        pq[ni * 2 + 0] += v2 * v2; pq[ni * 2 + 1] += v3 * v3;
                        uint32_t hp = pack_bf16x2(v2, v3);
                        float h0 = __uint_as_float(hp << 16);
                        float h1 = __uint_as_float(hp & 0xFFFF0000u);
                        *(uint32_t*)&g_yh[(size_t)(gr0 + 8) * DD + col] = hp;
                        *(uint32_t*)&g_yl[(size_t)(gr0 + 8) * DD + col] = pack_bf16x2(v2 - h0, v3 - h1);
                    }
                } else {
                    v0 = elu_f(v0); v1 = elu_f(v1); v2 = elu_f(v2); v3 = elu_f(v3);
                    if (gr0 < NN)
                        *(float2*)&g_h[(size_t)gr0 * DD + col] = make_float2(v0, v1);
                    if (gr0 + 8 < NN)
                        *(float2*)&g_h[(size_t)(gr0 + 8) * DD + col] = make_float2(v2, v3);
                }
            }
        }

        CP_WAIT0();
        __syncthreads();
        t = tn;
        stage ^= 1;
    }

    if (MODE == 0) {
#pragma unroll
        for (int j = 0; j < 8; j++) {
#pragma unroll
            for (int off = 4; off < 32; off <<= 1) {
                ps[j] += __shfl_xor_sync(0xffffffffu, ps[j], off);
                pq[j] += __shfl_xor_sync(0xffffffffu, pq[j], off);
            }
        }
        if (lane < 4) {
#pragma unroll
            for (int ni = 0; ni < 4; ni++) {
                int col = wn * 32 + lane * 2 + ni * 8;
                atomicAdd(&s_bn[col], ps[ni * 2 + 0]);
                atomicAdd(&s_bn[col + 1], ps[ni * 2 + 1]);
                atomicAdd(&s_bn[DD + col], pq[ni * 2 + 0]);
                atomicAdd(&s_bn[DD + col + 1], pq[ni * 2 + 1]);
            }
        }
        __syncthreads();
        if (tid < 2 * DD) g_part[blockIdx.x][tid] = s_bn[tid];
        __threadfence();
        __syncthreads();
        if (tid == 0) {
            int old = atomicAdd(&g_done, 1);
            s_last = ((old % nsm) == nsm - 1);
        }
        __syncthreads();
        // last-finishing CTA computes BN scale/shift for this layer
        if (s_last && tid < DD) {
            float s = 0.f, q = 0.f;
            for (int b = 0; b < nsm; b++) { s += g_part[b][tid]; q += g_part[b][DD + tid]; }
            float mu = s / (float)NN;
            float var = fmaxf(q / (float)NN - mu * mu, 0.f);
            float rs = rsqrtf(var + BN_EPS);
            float sc = rs * __ldg(&gamma[tid]);
            g_scale[tid] = sc;
            g_shift[tid] = __ldg(&beta[tid]) - mu * sc;
        }
    }
}

// ---------------- pooling + head ----------------
__device__ __forceinline__ int lower_bound_dev(const int* a, int n, int key) {
    int lo = 0, hi = n;
    while (lo < hi) {
        int mid = (lo + hi) >> 1;
        if (a[mid] < key) lo = mid + 1; else hi = mid;
    }
    return lo;
}

__global__ void pool_final(const int* __restrict__ batch,
                           const float* __restrict__ linW,
                           const float* __restrict__ linb,
                           float* __restrict__ out) {
    int g = blockIdx.x;
    int t = threadIdx.x;
    int lo = lower_bound_dev(batch, NN, g);
    int hi = lower_bound_dev(batch, NN, g + 1);
    float acc = 0.f;
    for (int r = lo; r < hi; ++r) acc += g_h[(size_t)r * DD + t];
    float cnt = fmaxf((float)(hi - lo), 1.f);
    float p = acc / cnt;
    float v0 = p * __ldg(&linW[t * 2 + 0]);
    float v1 = p * __ldg(&linW[t * 2 + 1]);
#pragma unroll
    for (int o = 16; o > 0; o >>= 1) {
        v0 += __shfl_down_sync(0xffffffffu, v0, o);
        v1 += __shfl_down_sync(0xffffffffu, v1, o);
    }
    __shared__ float s0[4], s1[4];
    if ((t & 31) == 0) { s0[t >> 5] = v0; s1[t >> 5] = v1; }
    __syncthreads();
    if (t == 0) {
        out[g * 2 + 0] = s0[0] + s0[1] + s0[2] + s0[3] + linb[0];
        out[g * 2 + 1] = s1[0] + s1[1] + s1[2] + s1[3] + linb[1];
    }
}

// ---------------- launch ----------------
extern "C" void kernel_launch(void* const* d_in, const int* in_sizes, int n_in,
                              void* d_out, int out_size) {
    const float* x     = (const float*)d_in[0];
    const int*   ei    = (const int*)d_in[1];
    const int*   batch = (const int*)d_in[2];
    const float* W1    = (const float*)d_in[3];
    const float* b1    = (const float*)d_in[4];
    const float* gamma = (const float*)d_in[5];
    const float* beta  = (const float*)d_in[6];
    const float* W2    = (const float*)d_in[7];
    const float* b2    = (const float*)d_in[8];
    const float* linW  = (const float*)d_in[9];
    const float* linb  = (const float*)d_in[10];
    float* out = (float*)d_out;

    cudaFuncSetAttribute(mma_gemm<0>, cudaFuncAttributeMaxDynamicSharedMemorySize, SMEM_MMA_BYTES);
    cudaFuncSetAttribute(mma_gemm<1>, cudaFuncAttributeMaxDynamicSharedMemorySize, SMEM_MMA_BYTES);

    int nsm = 148;
    cudaDeviceGetAttribute(&nsm, cudaDevAttrMultiProcessorCount, 0);
    if (nsm > NSM_MAX) nsm = NSM_MAX;
    if (nsm > NT) nsm = NT;

    const int nodeBlocks = (NN + 255) / 256;
    const int edgeBlocks = (EE + 255) / 256;
    const int aggBlocks  = (int)(((long)NN * 32 + 255) / 256);

    unsigned short* bhi_p;  unsigned short* blo_p;  float* h_p;
    cudaGetSymbolAddress((void**)&bhi_p, g_Bhi);
    cudaGetSymbolAddress((void**)&blo_p, g_Blo);
    cudaGetSymbolAddress((void**)&h_p, g_h);

    // weights conversion (y<8) + csr degree zero (y==8) in one launch
    convert_weights<<<dim3(nodeBlocks, 9), 256>>>(W1, W2);

    csr_hist<<<edgeBlocks, 256>>>(ei);
    scanA<<<NBLK_SCAN, SCAN_BLK>>>();
    scanB<<<1, 256>>>();
    scanC<<<nodeBlocks, 256>>>();
    csr_fill<<<edgeBlocks, 256>>>(ei);

    for (int l = 0; l < LL; l++) {
        gather_agg<<<aggBlocks, 256>>>(l == 0 ? x : h_p);
        mma_gemm<0><<<nsm, 256, SMEM_MMA_BYTES>>>(
            bhi_p + (size_t)(l * 2 + 0) * DD * DD, blo_p + (size_t)(l * 2 + 0) * DD * DD,
            b1 + l * DD, gamma + l * DD, beta + l * DD, nsm);
        mma_gemm<1><<<nsm, 256, SMEM_MMA_BYTES>>>(
            bhi_p + (size_t)(l * 2 + 1) * DD * DD, blo_p + (size_t)(l * 2 + 1) * DD * DD,
            b2 + l * DD, (const float*)nullptr, (const float*)nullptr, nsm);
    }

    pool_final<<<GG, 128>>>(batch, linW, linb, out);
}

// round 16
// speedup vs baseline: 1.0892x; 1.0892x over previous
#include <cuda_runtime.h>
#include <cuda_bf16.h>
#include <math.h>
#include <stdint.h>

#define NN 100000
#define EE 1600000
#define DD 128
#define LL 4
#define GG 512
#define BN_EPS 1e-5f
#define NPAD 100096
#define NSM_MAX 160

// ---------------- device scratch (no allocations allowed) ----------------
static __device__ __align__(16) float g_h[(size_t)NN * DD];
static __device__ __align__(16) unsigned short g_zh[(size_t)NPAD * DD];
static __device__ __align__(16) unsigned short g_zl[(size_t)NPAD * DD];
static __device__ __align__(16) unsigned short g_yh[(size_t)NPAD * DD];
static __device__ __align__(16) unsigned short g_yl[(size_t)NPAD * DD];
static __device__ float g_scale[DD];
static __device__ float g_shift[DD];
static __device__ __align__(16) unsigned short g_Bhi[8][DD * DD];
static __device__ __align__(16) unsigned short g_Blo[8][DD * DD];
static __device__ float g_part[NSM_MAX][2 * DD];
// CSR scratch
static __device__ int g_deg[NN];
static __device__ int g_rowptr[NN + 1];
static __device__ int g_cursor[NN];
static __device__ int g_csr_src[EE];
static __device__ int g_bsum[256];
static __device__ int g_boff[256];

#define SCAN_BLK 512
#define NBLK_SCAN ((NN + SCAN_BLK - 1) / SCAN_BLK)

__device__ __forceinline__ float elu_f(float x) {
    return x > 0.f ? x : expm1f(x);
}
__device__ __forceinline__ uint32_t smem_u32(const void* p) {
    uint32_t a;
    asm("{ .reg .u64 t; cvta.to.shared.u64 t, %1; cvt.u32.u64 %0, t; }" : "=r"(a) : "l"(p));
    return a;
}
__device__ __forceinline__ uint32_t pack_bf16x2(float lo, float hi) {
    uint32_t r;
    asm("cvt.rn.bf16x2.f32 %0, %1, %2;" : "=r"(r) : "f"(hi), "f"(lo));
    return r;
}
__device__ __forceinline__ void cp16(uint32_t dst, const void* src) {
    asm volatile("cp.async.cg.shared.global [%0], [%1], 16;" :: "r"(dst), "l"(src));
}
#define CP_COMMIT() asm volatile("cp.async.commit_group;")
#define CP_WAIT0()  asm volatile("cp.async.wait_group 0;")

__device__ __forceinline__ void ldsm_x4(uint32_t* r, uint32_t addr) {
    asm volatile("ldmatrix.sync.aligned.m8n8.x4.shared.b16 {%0,%1,%2,%3}, [%4];"
                 : "=r"(r[0]), "=r"(r[1]), "=r"(r[2]), "=r"(r[3]) : "r"(addr));
}
__device__ __forceinline__ void ldsm_x2(uint32_t* r, uint32_t addr) {
    asm volatile("ldmatrix.sync.aligned.m8n8.x2.shared.b16 {%0,%1}, [%2];"
                 : "=r"(r[0]), "=r"(r[1]) : "r"(addr));
}
__device__ __forceinline__ void mma_bf16(float* c, const uint32_t* a, const uint32_t* b) {
    asm volatile(
        "mma.sync.aligned.m16n8k16.row.col.f32.bf16.bf16.f32 "
        "{%0,%1,%2,%3}, {%4,%5,%6,%7}, {%8,%9}, {%0,%1,%2,%3};"
        : "+f"(c[0]), "+f"(c[1]), "+f"(c[2]), "+f"(c[3])
        : "r"(a[0]), "r"(a[1]), "r"(a[2]), "r"(a[3]), "r"(b[0]), "r"(b[1]));
}

// ---------------- weight conversion: W[k][n] -> B[n][k] split bf16 ------
__global__ void convert_weights(const float* __restrict__ W1, const float* __restrict__ W2) {
    int mat = blockIdx.y;
    const float* W = (mat & 1) ? (W2 + (size_t)(mat >> 1) * DD * DD)
                               : (W1 + (size_t)(mat >> 1) * DD * DD);
    int idx = blockIdx.x * blockDim.x + threadIdx.x;
    if (idx >= DD * DD) return;
    int n = idx / DD, k = idx % DD;
    float w = W[k * DD + n];
    uint32_t p = pack_bf16x2(w, 0.f);
    uint32_t hb = p & 0xFFFFu;
    float hf = __uint_as_float(hb << 16);
    uint32_t pl = pack_bf16x2(w - hf, 0.f);
    g_Bhi[mat][n * DD + k] = (unsigned short)hb;
    g_Blo[mat][n * DD + k] = (unsigned short)(pl & 0xFFFFu);
}

// ---------------- CSR build ----------------
__global__ void csr_zero() {
    int i = blockIdx.x * blockDim.x + threadIdx.x;
    if (i < NN) g_deg[i] = 0;
}
__global__ void csr_hist(const int* __restrict__ ei) {
    int e = blockIdx.x * blockDim.x + threadIdx.x;
    if (e < EE) atomicAdd(&g_deg[ei[EE + e]], 1);
}
__global__ void scanA() {
    __shared__ int s[SCAN_BLK];
    int b = blockIdx.x, t = threadIdx.x;
    int i = b * SCAN_BLK + t;
    int v = (i < NN) ? g_deg[i] : 0;
    s[t] = v;
    __syncthreads();
#pragma unroll
    for (int off = 1; off < SCAN_BLK; off <<= 1) {
        int u = (t >= off) ? s[t - off] : 0;
        __syncthreads();
        s[t] += u;
        __syncthreads();
    }
    if (i < NN) g_rowptr[i] = s[t] - v;
    if (t == SCAN_BLK - 1) g_bsum[b] = s[t];
}
__global__ void scanB() {
    __shared__ int s[256];
    int t = threadIdx.x;
    int v = (t < NBLK_SCAN) ? g_bsum[t] : 0;
    s[t] = v;
    __syncthreads();
#pragma unroll
    for (int off = 1; off < 256; off <<= 1) {
        int u = (t >= off) ? s[t - off] : 0;
        __syncthreads();
        s[t] += u;
        __syncthreads();
    }
    if (t < NBLK_SCAN) g_boff[t] = s[t] - v;
}
__global__ void scanC() {
    int i = blockIdx.x * blockDim.x + threadIdx.x;
    if (i < NN) {
        int r = g_rowptr[i] + g_boff[i / SCAN_BLK];
        g_rowptr[i] = r;
        g_cursor[i] = r;
    }
    if (i == 0) g_rowptr[NN] = EE;
}
__global__ void csr_fill(const int* __restrict__ ei) {
    int e = blockIdx.x * blockDim.x + threadIdx.x;
    if (e < EE) {
        int dst = ei[EE + e];
        int pos = atomicAdd(&g_cursor[dst], 1);
        g_csr_src[pos] = ei[e];
    }
}

// ------- aggregation: z[i] = H[i] + sum H[j], split-bf16 out -------------
__global__ void gather_agg(const float* __restrict__ H) {
    long tid = (long)blockIdx.x * blockDim.x + threadIdx.x;
    int node = (int)(tid >> 5);
    if (node >= NN) return;
    int c = (int)(tid & 31) << 2;
    float4 acc = *(const float4*)&H[(size_t)node * DD + c];
    int lo = __ldg(&g_rowptr[node]);
    int hi = __ldg(&g_rowptr[node + 1]);
    int j = lo;
    int s_next = (j < hi) ? __ldg(&g_csr_src[j]) : 0;
    while (j < hi) {
        int s = s_next;
        ++j;
        if (j < hi) s_next = __ldg(&g_csr_src[j]);
        float4 v = *(const float4*)&H[(size_t)s * DD + c];
        acc.x += v.x; acc.y += v.y; acc.z += v.z; acc.w += v.w;
    }
    uint32_t h01 = pack_bf16x2(acc.x, acc.y);
    uint32_t h23 = pack_bf16x2(acc.z, acc.w);
    float ax = __uint_as_float(h01 << 16);
    float ay = __uint_as_float(h01 & 0xFFFF0000u);
    float az = __uint_as_float(h23 << 16);
    float aw = __uint_as_float(h23 & 0xFFFF0000u);
    uint32_t l01 = pack_bf16x2(acc.x - ax, acc.y - ay);
    uint32_t l23 = pack_bf16x2(acc.z - az, acc.w - aw);
    *(uint2*)&g_zh[(size_t)node * DD + c] = make_uint2(h01, h23);
    *(uint2*)&g_zl[(size_t)node * DD + c] = make_uint2(l01, l23);
}

// ---------------- persistent HMMA GEMM: 512 threads, 4x4 warp grid -------
#define TSTRIDE 136
#define PTILE (128 * TSTRIDE * 2)
#define OFF_BH 0
#define OFF_BL PTILE
#define OFF_A0 (2 * PTILE)
#define OFF_A1 (4 * PTILE)
#define SMEM_MMA_BYTES (6 * PTILE)
#define NT ((NN + 127) / 128)
#define GTHREADS 512

template <int MODE>
__global__ __launch_bounds__(GTHREADS, 1) void mma_gemm(const unsigned short* __restrict__ Bhi,
                                                        const unsigned short* __restrict__ Blo,
                                                        const float* __restrict__ bias) {
    extern __shared__ char smem[];
    __shared__ float s_bn[2 * DD];
    __shared__ float s_scale[DD], s_shift[DD];

    const int tid = threadIdx.x;
    const int wid = tid >> 5;
    const int lane = tid & 31;
    const uint32_t sbase = smem_u32(smem);

    const unsigned short* AH = (MODE == 0) ? g_zh : g_yh;
    const unsigned short* AL = (MODE == 0) ? g_zl : g_yl;

    if (MODE == 0 && tid < 2 * DD) { s_bn[tid] = 0.f; }
    if (MODE == 1 && tid < DD) { s_scale[tid] = g_scale[tid]; s_shift[tid] = g_shift[tid]; }

#pragma unroll
    for (int it = 0; it < 4; it++) {
        int i = tid + it * GTHREADS;
        int r = i >> 4;
        int ci = (i & 15) * 16;
        cp16(sbase + OFF_BH + r * 272 + ci, (const char*)Bhi + r * 256 + ci);
        cp16(sbase + OFF_BL + r * 272 + ci, (const char*)Blo + r * 256 + ci);
    }
    int t = blockIdx.x;
    if (t < NT) {
        const unsigned short* srcH = AH + (size_t)t * 128 * DD;
        const unsigned short* srcL = AL + (size_t)t * 128 * DD;
#pragma unroll
        for (int it = 0; it < 4; it++) {
            int i = tid + it * GTHREADS;
            int r = i >> 4;
            int ci = (i & 15) * 16;
            cp16(sbase + OFF_A0 + r * 272 + ci, (const char*)srcH + r * 256 + ci);
            cp16(sbase + OFF_A0 + PTILE + r * 272 + ci, (const char*)srcL + r * 256 + ci);
        }
    }
    CP_COMMIT();
    CP_WAIT0();
    __syncthreads();

    const int wm = wid >> 2;                   // 0..3
    const int wn = wid & 3;                    // 0..3
    const int a_row = wm * 32 + (lane & 15);
    const int a_colsel = (lane >> 4) * 8;
    const int b_row = wn * 32 + (lane & 7);
    const int b_colsel = ((lane >> 3) & 1) * 8;
    const int ep_r = wm * 32 + (lane >> 2);
    const int cbase = wn * 32 + (lane & 3) * 2;

    float bv0[4], bv1[4];
#pragma unroll
    for (int ni = 0; ni < 4; ni++) {
        bv0[ni] = __ldg(&bias[cbase + ni * 8]);
        bv1[ni] = __ldg(&bias[cbase + ni * 8 + 1]);
    }

    float ps[8], pq[8];
#pragma unroll
    for (int j = 0; j < 8; j++) { ps[j] = 0.f; pq[j] = 0.f; }

    int stage = 0;
    while (t < NT) {
        int tn = t + gridDim.x;
        const uint32_t curA = sbase + (stage ? OFF_A1 : OFF_A0);
        const uint32_t nxtA = sbase + (stage ? OFF_A0 : OFF_A1);
        if (tn < NT) {
            const unsigned short* srcH = AH + (size_t)tn * 128 * DD;
            const unsigned short* srcL = AL + (size_t)tn * 128 * DD;
#pragma unroll
            for (int it = 0; it < 4; it++) {
                int i = tid + it * GTHREADS;
                int r = i >> 4;
                int ci = (i & 15) * 16;
                cp16(nxtA + r * 272 + ci, (const char*)srcH + r * 256 + ci);
                cp16(nxtA + PTILE + r * 272 + ci, (const char*)srcL + r * 256 + ci);
            }
        }
        CP_COMMIT();

        if (MODE == 1) {
#pragma unroll
            for (int it = 0; it < 4; it++) {
                int i = tid + it * GTHREADS;
                int r = i >> 4;
                int ci = (i & 15) * 16;
                uint32_t ah = curA + r * 272 + ci;
                uint32_t al = ah + PTILE;
                uint4 hv = *(uint4*)(smem + (ah - sbase));
                uint4 lv = *(uint4*)(smem + (al - sbase));
                uint32_t* hw = (uint32_t*)&hv;
                uint32_t* lw = (uint32_t*)&lv;
                int col0 = ci >> 1;
#pragma unroll
                for (int w = 0; w < 4; w++) {
                    int col = col0 + w * 2;
                    float v0 = __uint_as_float(hw[w] << 16) + __uint_as_float(lw[w] << 16);
                    float v1 = __uint_as_float(hw[w] & 0xFFFF0000u) +
                               __uint_as_float(lw[w] & 0xFFFF0000u);
                    v0 = elu_f(v0 * s_scale[col] + s_shift[col]);
                    v1 = elu_f(v1 * s_scale[col + 1] + s_shift[col + 1]);
                    uint32_t hp = pack_bf16x2(v0, v1);
                    float r0 = __uint_as_float(hp << 16);
                    float r1 = __uint_as_float(hp & 0xFFFF0000u);
                    hw[w] = hp;
                    lw[w] = pack_bf16x2(v0 - r0, v1 - r1);
                }
                *(uint4*)(smem + (ah - sbase)) = hv;
                *(uint4*)(smem + (al - sbase)) = lv;
            }
            __syncthreads();
        }

        float acc[2][4][4];
#pragma unroll
        for (int mi = 0; mi < 2; mi++)
#pragma unroll
            for (int ni = 0; ni < 4; ni++)
#pragma unroll
                for (int q = 0; q < 4; q++) acc[mi][ni][q] = 0.f;

        // pass 1+2: Ah x (Bh + Bl)
#pragma unroll
        for (int ks = 0; ks < 8; ks++) {
            uint32_t a[2][4];
#pragma unroll
            for (int mi = 0; mi < 2; mi++)
                ldsm_x4(a[mi], curA + (uint32_t)((a_row + mi * 16) * TSTRIDE
                                                 + ks * 16 + a_colsel) * 2);
            uint32_t b[4][2];
#pragma unroll
            for (int ni = 0; ni < 4; ni++)
                ldsm_x2(b[ni], sbase + OFF_BH + (uint32_t)((b_row + ni * 8) * TSTRIDE
                                                           + ks * 16 + b_colsel) * 2);
#pragma unroll
            for (int mi = 0; mi < 2; mi++)
#pragma unroll
                for (int ni = 0; ni < 4; ni++)
                    mma_bf16(acc[mi][ni], a[mi], b[ni]);
#pragma unroll
            for (int ni = 0; ni < 4; ni++)
                ldsm_x2(b[ni], sbase + OFF_BL + (uint32_t)((b_row + ni * 8) * TSTRIDE
                                                           + ks * 16 + b_colsel) * 2);
#pragma unroll
            for (int mi = 0; mi < 2; mi++)
#pragma unroll
                for (int ni = 0; ni < 4; ni++)
                    mma_bf16(acc[mi][ni], a[mi], b[ni]);
        }
        // pass 3: Al x Bh
#pragma unroll
        for (int ks = 0; ks < 8; ks++) {
            uint32_t a[2][4];
#pragma unroll
            for (int mi = 0; mi < 2; mi++)
                ldsm_x4(a[mi], curA + PTILE + (uint32_t)((a_row + mi * 16) * TSTRIDE
                                                         + ks * 16 + a_colsel) * 2);
            uint32_t b[4][2];
#pragma unroll
            for (int ni = 0; ni < 4; ni++)
                ldsm_x2(b[ni], sbase + OFF_BH + (uint32_t)((b_row + ni * 8) * TSTRIDE
                                                           + ks * 16 + b_colsel) * 2);
#pragma unroll
            for (int mi = 0; mi < 2; mi++)
#pragma unroll
                for (int ni = 0; ni < 4; ni++)
                    mma_bf16(acc[mi][ni], a[mi], b[ni]);
        }

        const int rowBase = t * 128;
#pragma unroll
        for (int ni = 0; ni < 4; ni++) {
            int col = cbase + ni * 8;
#pragma unroll
            for (int mi = 0; mi < 2; mi++) {
                int gr0 = rowBase + ep_r + mi * 16;
                float v0 = acc[mi][ni][0] + bv0[ni];
                float v1 = acc[mi][ni][1] + bv1[ni];
                float v2 = acc[mi][ni][2] + bv0[ni];
                float v3 = acc[mi][ni][3] + bv1[ni];
                if (MODE == 0) {
                    if (gr0 < NN) {
                        ps[ni * 2 + 0] += v0; ps[ni * 2 + 1] += v1;
                        pq[ni * 2 + 0] += v0 * v0; pq[ni * 2 + 1] += v1 * v1;
                        uint32_t hp = pack_bf16x2(v0, v1);
                        float h0 = __uint_as_float(hp << 16);
                        float h1 = __uint_as_float(hp & 0xFFFF0000u);
                        *(uint32_t*)&g_yh[(size_t)gr0 * DD + col] = hp;
                        *(uint32_t*)&g_yl[(size_t)gr0 * DD + col] = pack_bf16x2(v0 - h0, v1 - h1);
                    }
                    if (gr0 + 8 < NN) {
                        ps[ni * 2 + 0] += v2; ps[ni * 2 + 1] += v3;
                        pq[ni * 2 + 0] += v2 * v2; pq[ni * 2 + 1] += v3 * v3;
                        uint32_t hp = pack_bf16x2(v2, v3);
                        float h0 = __uint_as_float(hp << 16);
                        float h1 = __uint_as_float(hp & 0xFFFF0000u);
                        *(uint32_t*)&g_yh[(size_t)(gr0 + 8) * DD + col] = hp;
                        *(uint32_t*)&g_yl[(size_t)(gr0 + 8) * DD + col] = pack_bf16x2(v2 - h0, v3 - h1);
                    }
                } else {
                    v0 = elu_f(v0); v1 = elu_f(v1); v2 = elu_f(v2); v3 = elu_f(v3);
                    if (gr0 < NN)
                        *(float2*)&g_h[(size_t)gr0 * DD + col] = make_float2(v0, v1);
                    if (gr0 + 8 < NN)
                        *(float2*)&g_h[(size_t)(gr0 + 8) * DD + col] = make_float2(v2, v3);
                }
            }
        }

        CP_WAIT0();
        __syncthreads();
        t = tn;
        stage ^= 1;
    }

    if (MODE == 0) {
#pragma unroll
        for (int j = 0; j < 8; j++) {
#pragma unroll
            for (int off = 4; off < 32; off <<= 1) {
                ps[j] += __shfl_xor_sync(0xffffffffu, ps[j], off);
                pq[j] += __shfl_xor_sync(0xffffffffu, pq[j], off);
            }
        }
        if (lane < 4) {
#pragma unroll
            for (int ni = 0; ni < 4; ni++) {
                int col = wn * 32 + lane * 2 + ni * 8;
                atomicAdd(&s_bn[col], ps[ni * 2 + 0]);
                atomicAdd(&s_bn[col + 1], ps[ni * 2 + 1]);
                atomicAdd(&s_bn[DD + col], pq[ni * 2 + 0]);
                atomicAdd(&s_bn[DD + col + 1], pq[ni * 2 + 1]);
            }
        }
        __syncthreads();
        if (tid < 2 * DD) g_part[blockIdx.x][tid] = s_bn[tid];
    }
}

// ---------------- BN finalize ----------------
__global__ void bn_finalize(const float* __restrict__ gamma, const float* __restrict__ beta,
                            int nsm) {
    int t = threadIdx.x;
    if (t >= DD) return;
    float s = 0.f, q = 0.f;
    for (int b = 0; b < nsm; b++) { s += g_part[b][t]; q += g_part[b][DD + t]; }
    float mu = s / (float)NN;
    float var = fmaxf(q / (float)NN - mu * mu, 0.f);
    float rs = rsqrtf(var + BN_EPS);
    float sc = rs * gamma[t];
    g_scale[t] = sc;
    g_shift[t] = beta[t] - mu * sc;
}

// ---------------- pooling + head ----------------
__device__ __forceinline__ int lower_bound_dev(const int* a, int n, int key) {
    int lo = 0, hi = n;
    while (lo < hi) {
        int mid = (lo + hi) >> 1;
        if (a[mid] < key) lo = mid + 1; else hi = mid;
    }
    return lo;
}

__global__ void pool_final(const int* __restrict__ batch,
                           const float* __restrict__ linW,
                           const float* __restrict__ linb,
                           float* __restrict__ out) {
    int g = blockIdx.x;
    int t = threadIdx.x;
    int lo = lower_bound_dev(batch, NN, g);
    int hi = lower_bound_dev(batch, NN, g + 1);
    float acc = 0.f;
    for (int r = lo; r < hi; ++r) acc += g_h[(size_t)r * DD + t];
    float cnt = fmaxf((float)(hi - lo), 1.f);
    float p = acc / cnt;
    float v0 = p * __ldg(&linW[t * 2 + 0]);
    float v1 = p * __ldg(&linW[t * 2 + 1]);
#pragma unroll
    for (int o = 16; o > 0; o >>= 1) {
        v0 += __shfl_down_sync(0xffffffffu, v0, o);
        v1 += __shfl_down_sync(0xffffffffu, v1, o);
    }
    __shared__ float s0[4], s1[4];
    if ((t & 31) == 0) { s0[t >> 5] = v0; s1[t >> 5] = v1; }
    __syncthreads();
    if (t == 0) {
        out[g * 2 + 0] = s0[0] + s0[1] + s0[2] + s0[3] + linb[0];
        out[g * 2 + 1] = s1[0] + s1[1] + s1[2] + s1[3] + linb[1];
    }
}

// ---------------- launch ----------------
extern "C" void kernel_launch(void* const* d_in, const int* in_sizes, int n_in,
                              void* d_out, int out_size) {
    const float* x     = (const float*)d_in[0];
    const int*   ei    = (const int*)d_in[1];
    const int*   batch = (const int*)d_in[2];
    const float* W1    = (const float*)d_in[3];
    const float* b1    = (const float*)d_in[4];
    const float* gamma = (const float*)d_in[5];
    const float* beta  = (const float*)d_in[6];
    const float* W2    = (const float*)d_in[7];
    const float* b2    = (const float*)d_in[8];
    const float* linW  = (const float*)d_in[9];
    const float* linb  = (const float*)d_in[10];
    float* out = (float*)d_out;

    cudaFuncSetAttribute(mma_gemm<0>, cudaFuncAttributeMaxDynamicSharedMemorySize, SMEM_MMA_BYTES);
    cudaFuncSetAttribute(mma_gemm<1>, cudaFuncAttributeMaxDynamicSharedMemorySize, SMEM_MMA_BYTES);

    int nsm = 148;
    cudaDeviceGetAttribute(&nsm, cudaDevAttrMultiProcessorCount, 0);
    if (nsm > NSM_MAX) nsm = NSM_MAX;
    if (nsm > NT) nsm = NT;

    const int nodeBlocks = (NN + 255) / 256;
    const int edgeBlocks = (EE + 255) / 256;
    const int aggBlocks  = (int)(((long)NN * 32 + 255) / 256);

    unsigned short* bhi_p;  unsigned short* blo_p;  float* h_p;
    cudaGetSymbolAddress((void**)&bhi_p, g_Bhi);
    cudaGetSymbolAddress((void**)&blo_p, g_Blo);
    cudaGetSymbolAddress((void**)&h_p, g_h);

    convert_weights<<<dim3((DD * DD + 255) / 256, 8), 256>>>(W1, W2);

    csr_zero<<<nodeBlocks, 256>>>();
    csr_hist<<<edgeBlocks, 256>>>(ei);
    scanA<<<NBLK_SCAN, SCAN_BLK>>>();
    scanB<<<1, 256>>>();
    scanC<<<nodeBlocks, 256>>>();
    csr_fill<<<edgeBlocks, 256>>>(ei);

    for (int l = 0; l < LL; l++) {
        gather_agg<<<aggBlocks, 256>>>(l == 0 ? x : h_p);
        mma_gemm<0><<<nsm, GTHREADS, SMEM_MMA_BYTES>>>(
            bhi_p + (size_t)(l * 2 + 0) * DD * DD, blo_p + (size_t)(l * 2 + 0) * DD * DD,
            b1 + l * DD);
        bn_finalize<<<1, 128>>>(gamma + l * DD, beta + l * DD, nsm);
        mma_gemm<1><<<nsm, GTHREADS, SMEM_MMA_BYTES>>>(
            bhi_p + (size_t)(l * 2 + 1) * DD * DD, blo_p + (size_t)(l * 2 + 1) * DD * DD,
            b2 + l * DD);
    }

    pool_final<<<GG, 128>>>(batch, linW, linb, out);
}